// round 15
// baseline (speedup 1.0000x reference)
#include <cuda_runtime.h>
#include <cuda_fp16.h>
#include <math.h>

#define N_NODES 50000
#define N_EDGES 800000
#define IN_C    64
#define HID     128
#define OUT_C   2
#define N_GRAPHS 64
#define SCAN_NBLK 49           // ceil(50000/1024)
#define NT 1563                // ceil(50000/32) tiles
#define PERSIST_BLK 1184       // 8 blocks/SM * 148 SMs

// ---------------- scratch (zero-init at load; kernels restore invariant) ----
__device__ __align__(16) int   g_cnt_e [N_NODES];
__device__ float    g_dinv  [N_NODES];
__device__ int      g_off   [N_NODES + 1];
__device__ int      g_cursor[N_NODES];
__device__ int      g_csr   [N_EDGES];
__device__ int      g_part  [64];
__device__ int      g_tc1, g_tc2;             // tile-steal counters
__device__ unsigned g_h16   [N_NODES * 64];   // h as half2 pairs
__device__ float    g_pool  [N_GRAPHS * HID];
__device__ float    g_gcnt  [N_GRAPHS];

// ---------------- helpers ----------------
__device__ __forceinline__ unsigned f2tf(float f) {
    unsigned u;
    asm("cvt.rna.tf32.f32 %0, %1;" : "=r"(u) : "f"(f));
    return u;
}
__device__ __forceinline__ float4 h4_to_f4(uint2 u) {
    __half2 a = *(__half2*)&u.x;
    __half2 b = *(__half2*)&u.y;
    float2 fa = __half22float2(a);
    float2 fb = __half22float2(b);
    return make_float4(fa.x, fa.y, fb.x, fb.y);
}
__device__ __forceinline__ void mma_tf32(float* c, unsigned a0, unsigned a1,
                                         unsigned a2, unsigned a3,
                                         unsigned b0, unsigned b1) {
    asm volatile(
        "mma.sync.aligned.m16n8k8.row.col.f32.tf32.tf32.f32 "
        "{%0,%1,%2,%3}, {%4,%5,%6,%7}, {%8,%9}, {%0,%1,%2,%3};"
        : "+f"(c[0]), "+f"(c[1]), "+f"(c[2]), "+f"(c[3])
        : "r"(a0), "r"(a1), "r"(a2), "r"(a3), "r"(b0), "r"(b1));
}

// ---------------- degree (4 edges/thread) ----------------
__global__ void k_deg4(const int* __restrict__ dst) {
    int i4 = blockIdx.x * blockDim.x + threadIdx.x;
    if (i4 >= N_EDGES / 4) return;
    int4 d = ((const int4*)dst)[i4];
    atomicAdd(&g_cnt_e[d.x], 1);
    atomicAdd(&g_cnt_e[d.y], 1);
    atomicAdd(&g_cnt_e[d.z], 1);
    atomicAdd(&g_cnt_e[d.w], 1);
}

// ---------------- scan pass 1: per-block sums ----------------
__global__ void __launch_bounds__(1024) k_blocksum() {
    __shared__ int ws[32];
    int t = threadIdx.x, lane = t & 31, w = t >> 5;
    int i = blockIdx.x * 1024 + t;
    int v = (i < N_NODES) ? g_cnt_e[i] : 0;
    int s = v;
    #pragma unroll
    for (int d = 16; d > 0; d >>= 1) s += __shfl_xor_sync(0xffffffffu, s, d);
    if (lane == 0) ws[w] = s;
    __syncthreads();
    if (w == 0) {
        int x = ws[lane];
        #pragma unroll
        for (int d = 16; d > 0; d >>= 1) x += __shfl_xor_sync(0xffffffffu, x, d);
        if (lane == 0) g_part[blockIdx.x] = x;
    }
}

// ---------------- scan pass 2+3 fused: offsets; clears g_cnt_e; resets tc ----
__global__ void __launch_bounds__(1024) k_offsets() {
    __shared__ int ws[32];
    __shared__ int sExcl[64];
    __shared__ int w0s;
    int t = threadIdx.x, lane = t & 31, w = t >> 5;

    int pv = 0, px = 0;
    if (w < 2) {
        pv = (t < SCAN_NBLK) ? g_part[t] : 0;
        px = pv;
        #pragma unroll
        for (int d = 1; d < 32; d <<= 1) {
            int y = __shfl_up_sync(0xffffffffu, px, d);
            if (lane >= d) px += y;
        }
        if (w == 0 && lane == 31) w0s = px;
    }
    __syncthreads();
    if (w < 2) sExcl[t] = px - pv + (w == 1 ? w0s : 0);

    int i = blockIdx.x * 1024 + t;
    int v = (i < N_NODES) ? g_cnt_e[i] : 0;
    int x = v;
    #pragma unroll
    for (int d = 1; d < 32; d <<= 1) {
        int y = __shfl_up_sync(0xffffffffu, x, d);
        if (lane >= d) x += y;
    }
    if (lane == 31) ws[w] = x;
    __syncthreads();
    if (w == 0) {
        int y = ws[lane];
        #pragma unroll
        for (int d = 1; d < 32; d <<= 1) {
            int z = __shfl_up_sync(0xffffffffu, y, d);
            if (lane >= d) y += z;
        }
        ws[lane] = y;
    }
    __syncthreads();
    int excl = sExcl[blockIdx.x] + (w ? ws[w - 1] : 0) + x - v;
    if (i < N_NODES) {
        g_off[i]    = excl;
        g_cursor[i] = excl;
        g_dinv[i]   = rsqrtf((float)v + 1.0f);
        g_cnt_e[i]  = 0;
    }
    if (i == 0) {
        g_off[N_NODES] = N_EDGES;
        g_tc1 = 0;
        g_tc2 = 0;
    }
}

// ---------------- CSR build (1 edge/thread — measured fastest) ----------------
__global__ void k_csr(const int* __restrict__ src, const int* __restrict__ dst) {
    int e = blockIdx.x * blockDim.x + threadIdx.x;
    if (e >= N_EDGES) return;
    int d = dst[e];
    int pos = atomicAdd(&g_cursor[d], 1);
    g_csr[pos] = src[e];
}

// ---------------- fused layer 1 (persistent): agg + TF32 MMA + relu -> g_h16 -
__global__ void __launch_bounds__(256) k_fused1(const float4* __restrict__ X,
                                                const float4* __restrict__ W4,
                                                const float* __restrict__ b) {
    __shared__ __align__(16) unsigned sAu[32 * 68];
    __shared__ __align__(16) unsigned sWu[32 * 132];
    __shared__ int s_tile;
    int t = threadIdx.x, lane = t & 31, w = t >> 5;
    int c = lane & 15, half = lane >> 4;
    int warp_m = w & 1, warp_n = w >> 1;
    int tg = lane & 3, gid = lane >> 2;

    while (true) {
        if (t == 0) s_tile = atomicAdd(&g_tc1, 1);
        __syncthreads();                 // broadcast + protects sAu reuse
        int tile = s_tile;
        if (tile >= NT) break;
        int row0 = tile * 32;

        // ---- aggregation (warp per node; halves interleave edges) ----
        #pragma unroll 1
        for (int it = 0; it < 4; it++) {
            int n = row0 + it * 8 + w;
            int nl = it * 8 + w;
            if (n < N_NODES) {
                float dn = g_dinv[n];
                float4 acc = make_float4(0.f, 0.f, 0.f, 0.f);
                if (half == 0) {
                    float4 v = X[(size_t)n * 16 + c];
                    acc.x = dn * v.x; acc.y = dn * v.y; acc.z = dn * v.z; acc.w = dn * v.w;
                }
                int e  = g_off[n] + half;
                int e1 = g_off[n + 1];
                for (; e < e1; e += 2) {
                    int s = g_csr[e];
                    float ds = g_dinv[s];
                    float4 v = X[(size_t)s * 16 + c];
                    acc.x += ds * v.x; acc.y += ds * v.y; acc.z += ds * v.z; acc.w += ds * v.w;
                }
                acc.x += __shfl_xor_sync(0xffffffffu, acc.x, 16);
                acc.y += __shfl_xor_sync(0xffffffffu, acc.y, 16);
                acc.z += __shfl_xor_sync(0xffffffffu, acc.z, 16);
                acc.w += __shfl_xor_sync(0xffffffffu, acc.w, 16);
                if (half == 0) {
                    acc.x *= dn; acc.y *= dn; acc.z *= dn; acc.w *= dn;
                    ((uint4*)sAu)[nl * 17 + c] =
                        make_uint4(f2tf(acc.x), f2tf(acc.y), f2tf(acc.z), f2tf(acc.w));
                }
            } else if (half == 0) {
                ((uint4*)sAu)[nl * 17 + c] = make_uint4(0u, 0u, 0u, 0u);
            }
        }

        // ---- GEMM via tf32 mma: warp grid 2x4 ----
        float acc[4][4];
        #pragma unroll
        for (int nt = 0; nt < 4; nt++)
            #pragma unroll
            for (int i = 0; i < 4; i++) acc[nt][i] = 0.f;

        for (int kt0 = 0; kt0 < 64; kt0 += 32) {
            __syncthreads();
            for (int i = t; i < 32 * 32; i += 256) {
                int kr = i >> 5, n4 = i & 31;
                float4 wv = W4[(kt0 + kr) * 32 + n4];
                ((uint4*)sWu)[kr * 33 + n4] =
                    make_uint4(f2tf(wv.x), f2tf(wv.y), f2tf(wv.z), f2tf(wv.w));
            }
            __syncthreads();
            #pragma unroll
            for (int ks = 0; ks < 4; ks++) {
                int kb = kt0 + ks * 8;
                int ar = warp_m * 16 + gid;
                unsigned a0 = sAu[ar * 68 + kb + tg];
                unsigned a1 = sAu[(ar + 8) * 68 + kb + tg];
                unsigned a2 = sAu[ar * 68 + kb + tg + 4];
                unsigned a3 = sAu[(ar + 8) * 68 + kb + tg + 4];
                int kl = ks * 8;
                #pragma unroll
                for (int nt = 0; nt < 4; nt++) {
                    int nc = warp_n * 32 + nt * 8 + gid;
                    unsigned b0 = sWu[(kl + tg) * 132 + nc];
                    unsigned b1 = sWu[(kl + tg + 4) * 132 + nc];
                    mma_tf32(acc[nt], a0, a1, a2, a3, b0, b1);
                }
            }
        }

        // ---- epilogue: bias + relu -> g_h16 ----
        #pragma unroll
        for (int nt = 0; nt < 4; nt++) {
            int col = warp_n * 32 + nt * 8 + 2 * tg;
            float bb0 = b[col], bb1 = b[col + 1];
            int gr0 = row0 + warp_m * 16 + gid;
            if (gr0 < N_NODES) {
                __half2 hv = __floats2half2_rn(fmaxf(acc[nt][0] + bb0, 0.f),
                                               fmaxf(acc[nt][1] + bb1, 0.f));
                g_h16[(size_t)gr0 * 64 + (col >> 1)] = *(unsigned*)&hv;
            }
            int gr1 = gr0 + 8;
            if (gr1 < N_NODES) {
                __half2 hv = __floats2half2_rn(fmaxf(acc[nt][2] + bb0, 0.f),
                                               fmaxf(acc[nt][3] + bb1, 0.f));
                g_h16[(size_t)gr1 * 64 + (col >> 1)] = *(unsigned*)&hv;
            }
        }
    }
}

// ---------------- fused layer 2 (persistent): agg + TF32 MMA + mean-pool -----
__global__ void __launch_bounds__(256) k_fused2(const float4* __restrict__ W4,
                                                const float* __restrict__ b,
                                                const int* __restrict__ batch) {
    __shared__ __align__(16) unsigned sAu[32 * 132];
    __shared__ __align__(16) unsigned sWu[16 * 132];
    __shared__ int s_tile;
    int t = threadIdx.x, lane = t & 31, w = t >> 5;
    int warp_m = w & 1, warp_n = w >> 1;
    int tg = lane & 3, gid = lane >> 2;
    const uint2* H16 = (const uint2*)g_h16;

    while (true) {
        if (t == 0) s_tile = atomicAdd(&g_tc2, 1);
        __syncthreads();
        int tile = s_tile;
        if (tile >= NT) break;
        int row0 = tile * 32;

        // ---- aggregation (warp per node; lane = 4-feat chunk) ----
        #pragma unroll 1
        for (int it = 0; it < 4; it++) {
            int n = row0 + it * 8 + w;
            int nl = it * 8 + w;
            if (n < N_NODES) {
                float dn = g_dinv[n];
                float4 v = h4_to_f4(H16[(size_t)n * 32 + lane]);
                float4 acc;
                acc.x = dn * v.x; acc.y = dn * v.y; acc.z = dn * v.z; acc.w = dn * v.w;
                int e  = g_off[n];
                int e1 = g_off[n + 1];
                for (; e + 1 < e1; e += 2) {
                    int s0 = g_csr[e], s1 = g_csr[e + 1];
                    float d0 = g_dinv[s0], d1 = g_dinv[s1];
                    float4 v0 = h4_to_f4(H16[(size_t)s0 * 32 + lane]);
                    float4 v1 = h4_to_f4(H16[(size_t)s1 * 32 + lane]);
                    acc.x += d0 * v0.x + d1 * v1.x;
                    acc.y += d0 * v0.y + d1 * v1.y;
                    acc.z += d0 * v0.z + d1 * v1.z;
                    acc.w += d0 * v0.w + d1 * v1.w;
                }
                if (e < e1) {
                    int s0 = g_csr[e];
                    float d0 = g_dinv[s0];
                    float4 v0 = h4_to_f4(H16[(size_t)s0 * 32 + lane]);
                    acc.x += d0 * v0.x; acc.y += d0 * v0.y; acc.z += d0 * v0.z; acc.w += d0 * v0.w;
                }
                acc.x *= dn; acc.y *= dn; acc.z *= dn; acc.w *= dn;
                ((uint4*)sAu)[nl * 33 + lane] =
                    make_uint4(f2tf(acc.x), f2tf(acc.y), f2tf(acc.z), f2tf(acc.w));
            } else {
                ((uint4*)sAu)[nl * 33 + lane] = make_uint4(0u, 0u, 0u, 0u);
            }
        }

        // ---- GEMM via tf32 mma ----
        float acc[4][4];
        #pragma unroll
        for (int nt = 0; nt < 4; nt++)
            #pragma unroll
            for (int i = 0; i < 4; i++) acc[nt][i] = 0.f;

        for (int kt0 = 0; kt0 < 128; kt0 += 16) {
            __syncthreads();
            for (int i = t; i < 16 * 32; i += 256) {
                int kr = i >> 5, n4 = i & 31;
                float4 wv = W4[(kt0 + kr) * 32 + n4];
                ((uint4*)sWu)[kr * 33 + n4] =
                    make_uint4(f2tf(wv.x), f2tf(wv.y), f2tf(wv.z), f2tf(wv.w));
            }
            __syncthreads();
            #pragma unroll
            for (int ks = 0; ks < 2; ks++) {
                int kb = kt0 + ks * 8;
                int ar = warp_m * 16 + gid;
                unsigned a0 = sAu[ar * 132 + kb + tg];
                unsigned a1 = sAu[(ar + 8) * 132 + kb + tg];
                unsigned a2 = sAu[ar * 132 + kb + tg + 4];
                unsigned a3 = sAu[(ar + 8) * 132 + kb + tg + 4];
                int kl = ks * 8;
                #pragma unroll
                for (int nt = 0; nt < 4; nt++) {
                    int nc = warp_n * 32 + nt * 8 + gid;
                    unsigned b0 = sWu[(kl + tg) * 132 + nc];
                    unsigned b1 = sWu[(kl + tg + 4) * 132 + nc];
                    mma_tf32(acc[nt], a0, a1, a2, a3, b0, b1);
                }
            }
        }
        __syncthreads();

        // ---- stage outputs into sA as fp32, then pool ----
        float* sAf = (float*)sAu;
        #pragma unroll
        for (int nt = 0; nt < 4; nt++) {
            int col = warp_n * 32 + nt * 8 + 2 * tg;
            float bb0 = b[col], bb1 = b[col + 1];
            int r0_ = warp_m * 16 + gid;
            sAf[r0_ * 132 + col]     = acc[nt][0] + bb0;
            sAf[r0_ * 132 + col + 1] = acc[nt][1] + bb1;
            sAf[(r0_ + 8) * 132 + col]     = acc[nt][2] + bb0;
            sAf[(r0_ + 8) * 132 + col + 1] = acc[nt][3] + bb1;
        }
        __syncthreads();

        int j = t & 127, half2_ = t >> 7;
        int rbeg = half2_ * 16;
        int rend = min(rbeg + 16, N_NODES - row0);
        float pacc = 0.f;
        int cur = -1, cnt = 0;
        for (int r = rbeg; r < rend; r++) {
            int bb = __ldg(&batch[row0 + r]);
            if (bb != cur) {
                if (cur >= 0) {
                    atomicAdd(&g_pool[cur * HID + j], pacc);
                    if (j == 0) atomicAdd(&g_gcnt[cur], (float)cnt);
                }
                cur = bb; pacc = 0.f; cnt = 0;
            }
            pacc += sAf[r * 132 + j];
            cnt++;
        }
        if (cur >= 0) {
            atomicAdd(&g_pool[cur * HID + j], pacc);
            if (j == 0) atomicAdd(&g_gcnt[cur], (float)cnt);
        }
    }
}

// ---------------- fused MLP head (clears g_pool / g_gcnt) ----------------
__global__ void __launch_bounds__(128) k_mlp(const float* __restrict__ Wm1,
                                             const float* __restrict__ bm1,
                                             const float* __restrict__ Wm2,
                                             const float* __restrict__ bm2,
                                             float* __restrict__ out) {
    __shared__ float grow[HID];
    __shared__ float r0[HID], r1[HID];
    int r = blockIdx.x;
    int j = threadIdx.x;
    grow[j] = g_pool[r * HID + j] / fmaxf(g_gcnt[r], 1.0f);
    g_pool[r * HID + j] = 0.f;
    __syncthreads();
    if (j == 0) g_gcnt[r] = 0.f;
    float acc = bm1[j];
    #pragma unroll 8
    for (int k = 0; k < HID; k++) acc += grow[k] * Wm1[k * HID + j];
    float h = fmaxf(acc, 0.f);
    r0[j] = h * Wm2[j * OUT_C + 0];
    r1[j] = h * Wm2[j * OUT_C + 1];
    __syncthreads();
    #pragma unroll
    for (int s = 64; s > 0; s >>= 1) {
        if (j < s) { r0[j] += r0[j + s]; r1[j] += r1[j + s]; }
        __syncthreads();
    }
    if (j == 0) {
        out[r * OUT_C + 0] = r0[0] + bm2[0];
        out[r * OUT_C + 1] = r1[0] + bm2[1];
    }
}

// ---------------- launch ----------------
static inline int cdiv(int a, int b) { return (a + b - 1) / b; }

extern "C" void kernel_launch(void* const* d_in, const int* in_sizes, int n_in,
                              void* d_out, int out_size) {
    const float* x    = (const float*)d_in[0];
    const int*   ei   = (const int*)d_in[1];
    const int*   src  = ei;
    const int*   dst  = ei + N_EDGES;
    const int*   batch= (const int*)d_in[2];
    const float* W1  = (const float*)d_in[3];
    const float* b1  = (const float*)d_in[4];
    const float* W2  = (const float*)d_in[5];
    const float* b2  = (const float*)d_in[6];
    const float* Wm1 = (const float*)d_in[7];
    const float* bm1 = (const float*)d_in[8];
    const float* Wm2 = (const float*)d_in[9];
    const float* bm2 = (const float*)d_in[10];
    float* out = (float*)d_out;

    const int T = 256;

    k_deg4    <<<cdiv(N_EDGES / 4, T), T>>>(dst);
    k_blocksum<<<SCAN_NBLK, 1024>>>();
    k_offsets <<<SCAN_NBLK, 1024>>>();
    k_csr     <<<cdiv(N_EDGES, T), T>>>(src, dst);

    k_fused1<<<PERSIST_BLK, 256>>>((const float4*)x, (const float4*)W1, b1);
    k_fused2<<<PERSIST_BLK, 256>>>((const float4*)W2, b2, batch);

    k_mlp<<<N_GRAPHS, HID>>>(Wm1, bm1, Wm2, bm2, out);
}

// round 16
// speedup vs baseline: 1.0318x; 1.0318x over previous
#include <cuda_runtime.h>
#include <cuda_fp16.h>
#include <math.h>

#define N_NODES 50000
#define N_EDGES 800000
#define IN_C    64
#define HID     128
#define OUT_C   2
#define N_GRAPHS 64
#define SCAN_NBLK 49   // ceil(50000/1024)

// ---------------- scratch (zero-init at load; kernels restore invariant) ----
__device__ __align__(16) int   g_cnt_e [N_NODES];
__device__ float    g_dinv  [N_NODES];
__device__ int      g_off   [N_NODES + 1];
__device__ int      g_cursor[N_NODES];
__device__ int      g_csr   [N_EDGES];
__device__ int      g_part  [64];
__device__ unsigned g_h16   [N_NODES * 64];   // h as half2 pairs: 128 halves/node
__device__ float    g_pool  [N_GRAPHS * HID];
__device__ float    g_gcnt  [N_GRAPHS];

// ---------------- helpers ----------------
__device__ __forceinline__ unsigned f2tf(float f) {
    unsigned u;
    asm("cvt.rna.tf32.f32 %0, %1;" : "=r"(u) : "f"(f));
    return u;
}
__device__ __forceinline__ float4 h4_to_f4(uint2 u) {
    __half2 a = *(__half2*)&u.x;
    __half2 b = *(__half2*)&u.y;
    float2 fa = __half22float2(a);
    float2 fb = __half22float2(b);
    return make_float4(fa.x, fa.y, fb.x, fb.y);
}
__device__ __forceinline__ void mma_tf32(float* c, unsigned a0, unsigned a1,
                                         unsigned a2, unsigned a3,
                                         unsigned b0, unsigned b1) {
    asm volatile(
        "mma.sync.aligned.m16n8k8.row.col.f32.tf32.tf32.f32 "
        "{%0,%1,%2,%3}, {%4,%5,%6,%7}, {%8,%9}, {%0,%1,%2,%3};"
        : "+f"(c[0]), "+f"(c[1]), "+f"(c[2]), "+f"(c[3])
        : "r"(a0), "r"(a1), "r"(a2), "r"(a3), "r"(b0), "r"(b1));
}

// ---------------- degree (4 edges/thread) ----------------
__global__ void k_deg4(const int* __restrict__ dst) {
    int i4 = blockIdx.x * blockDim.x + threadIdx.x;
    if (i4 >= N_EDGES / 4) return;
    int4 d = ((const int4*)dst)[i4];
    atomicAdd(&g_cnt_e[d.x], 1);
    atomicAdd(&g_cnt_e[d.y], 1);
    atomicAdd(&g_cnt_e[d.z], 1);
    atomicAdd(&g_cnt_e[d.w], 1);
}

// ---------------- scan pass 1: per-block sums ----------------
__global__ void __launch_bounds__(1024) k_blocksum() {
    __shared__ int ws[32];
    int t = threadIdx.x, lane = t & 31, w = t >> 5;
    int i = blockIdx.x * 1024 + t;
    int v = (i < N_NODES) ? g_cnt_e[i] : 0;
    int s = v;
    #pragma unroll
    for (int d = 16; d > 0; d >>= 1) s += __shfl_xor_sync(0xffffffffu, s, d);
    if (lane == 0) ws[w] = s;
    __syncthreads();
    if (w == 0) {
        int x = ws[lane];
        #pragma unroll
        for (int d = 16; d > 0; d >>= 1) x += __shfl_xor_sync(0xffffffffu, x, d);
        if (lane == 0) g_part[blockIdx.x] = x;
    }
}

// ---------------- scan pass 2+3 fused: offsets; clears g_cnt_e ----------------
__global__ void __launch_bounds__(1024) k_offsets() {
    __shared__ int ws[32];
    __shared__ int sExcl[64];
    __shared__ int w0s;
    int t = threadIdx.x, lane = t & 31, w = t >> 5;

    int pv = 0, px = 0;
    if (w < 2) {
        pv = (t < SCAN_NBLK) ? g_part[t] : 0;
        px = pv;
        #pragma unroll
        for (int d = 1; d < 32; d <<= 1) {
            int y = __shfl_up_sync(0xffffffffu, px, d);
            if (lane >= d) px += y;
        }
        if (w == 0 && lane == 31) w0s = px;
    }
    __syncthreads();
    if (w < 2) sExcl[t] = px - pv + (w == 1 ? w0s : 0);

    int i = blockIdx.x * 1024 + t;
    int v = (i < N_NODES) ? g_cnt_e[i] : 0;
    int x = v;
    #pragma unroll
    for (int d = 1; d < 32; d <<= 1) {
        int y = __shfl_up_sync(0xffffffffu, x, d);
        if (lane >= d) x += y;
    }
    if (lane == 31) ws[w] = x;
    __syncthreads();
    if (w == 0) {
        int y = ws[lane];
        #pragma unroll
        for (int d = 1; d < 32; d <<= 1) {
            int z = __shfl_up_sync(0xffffffffu, y, d);
            if (lane >= d) y += z;
        }
        ws[lane] = y;
    }
    __syncthreads();
    int excl = sExcl[blockIdx.x] + (w ? ws[w - 1] : 0) + x - v;
    if (i < N_NODES) {
        g_off[i]    = excl;
        g_cursor[i] = excl;
        g_dinv[i]   = rsqrtf((float)v + 1.0f);
        g_cnt_e[i]  = 0;
    }
    if (i == 0) g_off[N_NODES] = N_EDGES;
}

// ---------------- CSR build (1 edge/thread — measured fastest) ----------------
__global__ void k_csr(const int* __restrict__ src, const int* __restrict__ dst) {
    int e = blockIdx.x * blockDim.x + threadIdx.x;
    if (e >= N_EDGES) return;
    int d = dst[e];
    int pos = atomicAdd(&g_cursor[d], 1);
    g_csr[pos] = src[e];
}

// ---------------- fused layer 1: agg(x,64) + TF32 MMA + relu -> g_h16 --------
// 32 nodes/block. sA 32x68 (8.7 KB) + sW 32x136 (17.4 KB) = 26.1 KB -> 8 blk/SM.
__global__ void __launch_bounds__(256) k_fused1(const float4* __restrict__ X,
                                                const float4* __restrict__ W4,
                                                const float* __restrict__ b) {
    __shared__ __align__(16) unsigned sAu[32 * 68];
    __shared__ __align__(16) unsigned sWu[32 * 136];
    int t = threadIdx.x, lane = t & 31, w = t >> 5;
    int row0 = blockIdx.x * 32;

    // ---- aggregation (warp per node; halves interleave edges; pipelined) ----
    int c = lane & 15, half = lane >> 4;
    #pragma unroll 1
    for (int it = 0; it < 4; it++) {
        int n = row0 + it * 8 + w;
        int nl = it * 8 + w;
        if (n < N_NODES) {
            float dn = g_dinv[n];
            float4 acc = make_float4(0.f, 0.f, 0.f, 0.f);
            if (half == 0) {
                float4 v = X[(size_t)n * 16 + c];
                acc.x = dn * v.x; acc.y = dn * v.y; acc.z = dn * v.z; acc.w = dn * v.w;
            }
            int e  = g_off[n] + half;
            int e1 = g_off[n + 1];
            if (e < e1) {
                int s = g_csr[e];
                float ds = g_dinv[s];
                while (true) {
                    int en = e + 2;
                    int sn = 0; float dsn = 0.f;
                    bool more = (en < e1);
                    if (more) { sn = g_csr[en]; dsn = g_dinv[sn]; }
                    float4 v = X[(size_t)s * 16 + c];
                    acc.x += ds * v.x; acc.y += ds * v.y;
                    acc.z += ds * v.z; acc.w += ds * v.w;
                    if (!more) break;
                    e = en; s = sn; ds = dsn;
                }
            }
            acc.x += __shfl_xor_sync(0xffffffffu, acc.x, 16);
            acc.y += __shfl_xor_sync(0xffffffffu, acc.y, 16);
            acc.z += __shfl_xor_sync(0xffffffffu, acc.z, 16);
            acc.w += __shfl_xor_sync(0xffffffffu, acc.w, 16);
            if (half == 0) {
                acc.x *= dn; acc.y *= dn; acc.z *= dn; acc.w *= dn;
                ((uint4*)sAu)[nl * 17 + c] =
                    make_uint4(f2tf(acc.x), f2tf(acc.y), f2tf(acc.z), f2tf(acc.w));
            }
        } else if (half == 0) {
            ((uint4*)sAu)[nl * 17 + c] = make_uint4(0u, 0u, 0u, 0u);
        }
    }

    // ---- GEMM via tf32 mma: warp grid 2x4 (16 rows x 32 cols each) ----
    int warp_m = w & 1, warp_n = w >> 1;
    int tg = lane & 3, gid = lane >> 2;
    float acc[4][4];
    #pragma unroll
    for (int nt = 0; nt < 4; nt++)
        #pragma unroll
        for (int i = 0; i < 4; i++) acc[nt][i] = 0.f;

    for (int kt0 = 0; kt0 < 64; kt0 += 32) {
        __syncthreads();
        for (int i = t; i < 32 * 32; i += 256) {
            int kr = i >> 5, n4 = i & 31;
            float4 wv = W4[(kt0 + kr) * 32 + n4];
            ((uint4*)sWu)[kr * 34 + n4] =
                make_uint4(f2tf(wv.x), f2tf(wv.y), f2tf(wv.z), f2tf(wv.w));
        }
        __syncthreads();
        #pragma unroll
        for (int ks = 0; ks < 4; ks++) {
            int kb = kt0 + ks * 8;
            int ar = warp_m * 16 + gid;
            unsigned a0 = sAu[ar * 68 + kb + tg];
            unsigned a1 = sAu[(ar + 8) * 68 + kb + tg];
            unsigned a2 = sAu[ar * 68 + kb + tg + 4];
            unsigned a3 = sAu[(ar + 8) * 68 + kb + tg + 4];
            int kl = ks * 8;
            #pragma unroll
            for (int nt = 0; nt < 4; nt++) {
                int nc = warp_n * 32 + nt * 8 + gid;
                unsigned b0 = sWu[(kl + tg) * 136 + nc];
                unsigned b1 = sWu[(kl + tg + 4) * 136 + nc];
                mma_tf32(acc[nt], a0, a1, a2, a3, b0, b1);
            }
        }
    }

    // ---- epilogue: bias + relu -> g_h16 (half2 per 2 cols) ----
    #pragma unroll
    for (int nt = 0; nt < 4; nt++) {
        int col = warp_n * 32 + nt * 8 + 2 * tg;
        float bb0 = b[col], bb1 = b[col + 1];
        int gr0 = row0 + warp_m * 16 + gid;
        if (gr0 < N_NODES) {
            __half2 hv = __floats2half2_rn(fmaxf(acc[nt][0] + bb0, 0.f),
                                           fmaxf(acc[nt][1] + bb1, 0.f));
            g_h16[(size_t)gr0 * 64 + (col >> 1)] = *(unsigned*)&hv;
        }
        int gr1 = gr0 + 8;
        if (gr1 < N_NODES) {
            __half2 hv = __floats2half2_rn(fmaxf(acc[nt][2] + bb0, 0.f),
                                           fmaxf(acc[nt][3] + bb1, 0.f));
            g_h16[(size_t)gr1 * 64 + (col >> 1)] = *(unsigned*)&hv;
        }
    }
}

// ---------------- fused layer 2: agg(g_h16,128) + TF32 MMA + mean-pool -------
// 32 nodes/block. sA 32x132 (16.9 KB) + sW 16x136 (8.7 KB) = 25.6 KB -> 8 blk/SM.
__global__ void __launch_bounds__(256) k_fused2(const float4* __restrict__ W4,
                                                const float* __restrict__ b,
                                                const int* __restrict__ batch) {
    __shared__ __align__(16) unsigned sAu[32 * 132];
    __shared__ __align__(16) unsigned sWu[16 * 136];
    int t = threadIdx.x, lane = t & 31, w = t >> 5;
    int row0 = blockIdx.x * 32;
    const uint2* H16 = (const uint2*)g_h16;

    // ---- aggregation (warp per node; lane = 4-feat chunk; pipelined pairs) ----
    #pragma unroll 1
    for (int it = 0; it < 4; it++) {
        int n = row0 + it * 8 + w;
        int nl = it * 8 + w;
        if (n < N_NODES) {
            float dn = g_dinv[n];
            float4 v = h4_to_f4(H16[(size_t)n * 32 + lane]);
            float4 acc;
            acc.x = dn * v.x; acc.y = dn * v.y; acc.z = dn * v.z; acc.w = dn * v.w;
            int beg = g_off[n];
            int e1  = g_off[n + 1];
            int cntE = e1 - beg;
            int pairs = cntE >> 1;
            if (pairs > 0) {
                int ee = beg;
                int s0 = g_csr[ee], s1 = g_csr[ee + 1];
                float d0 = g_dinv[s0], d1 = g_dinv[s1];
                for (int p = 0; p < pairs; p++) {
                    int ns0 = 0, ns1 = 0; float nd0 = 0.f, nd1 = 0.f;
                    if (p + 1 < pairs) {
                        ns0 = g_csr[ee + 2]; ns1 = g_csr[ee + 3];
                        nd0 = g_dinv[ns0];   nd1 = g_dinv[ns1];
                    }
                    float4 v0 = h4_to_f4(H16[(size_t)s0 * 32 + lane]);
                    float4 v1 = h4_to_f4(H16[(size_t)s1 * 32 + lane]);
                    acc.x += d0 * v0.x + d1 * v1.x;
                    acc.y += d0 * v0.y + d1 * v1.y;
                    acc.z += d0 * v0.z + d1 * v1.z;
                    acc.w += d0 * v0.w + d1 * v1.w;
                    s0 = ns0; s1 = ns1; d0 = nd0; d1 = nd1; ee += 2;
                }
            }
            if (cntE & 1) {
                int s0 = g_csr[beg + (cntE & ~1)];
                float d0 = g_dinv[s0];
                float4 v0 = h4_to_f4(H16[(size_t)s0 * 32 + lane]);
                acc.x += d0 * v0.x; acc.y += d0 * v0.y;
                acc.z += d0 * v0.z; acc.w += d0 * v0.w;
            }
            acc.x *= dn; acc.y *= dn; acc.z *= dn; acc.w *= dn;
            ((uint4*)sAu)[nl * 33 + lane] =
                make_uint4(f2tf(acc.x), f2tf(acc.y), f2tf(acc.z), f2tf(acc.w));
        } else {
            ((uint4*)sAu)[nl * 33 + lane] = make_uint4(0u, 0u, 0u, 0u);
        }
    }

    // ---- GEMM via tf32 mma: warp grid 2x4 ----
    int warp_m = w & 1, warp_n = w >> 1;
    int tg = lane & 3, gid = lane >> 2;
    float acc[4][4];
    #pragma unroll
    for (int nt = 0; nt < 4; nt++)
        #pragma unroll
        for (int i = 0; i < 4; i++) acc[nt][i] = 0.f;

    for (int kt0 = 0; kt0 < 128; kt0 += 16) {
        __syncthreads();
        for (int i = t; i < 16 * 32; i += 256) {
            int kr = i >> 5, n4 = i & 31;
            float4 wv = W4[(kt0 + kr) * 32 + n4];
            ((uint4*)sWu)[kr * 34 + n4] =
                make_uint4(f2tf(wv.x), f2tf(wv.y), f2tf(wv.z), f2tf(wv.w));
        }
        __syncthreads();
        #pragma unroll
        for (int ks = 0; ks < 2; ks++) {
            int kb = kt0 + ks * 8;
            int ar = warp_m * 16 + gid;
            unsigned a0 = sAu[ar * 132 + kb + tg];
            unsigned a1 = sAu[(ar + 8) * 132 + kb + tg];
            unsigned a2 = sAu[ar * 132 + kb + tg + 4];
            unsigned a3 = sAu[(ar + 8) * 132 + kb + tg + 4];
            int kl = ks * 8;
            #pragma unroll
            for (int nt = 0; nt < 4; nt++) {
                int nc = warp_n * 32 + nt * 8 + gid;
                unsigned b0 = sWu[(kl + tg) * 136 + nc];
                unsigned b1 = sWu[(kl + tg + 4) * 136 + nc];
                mma_tf32(acc[nt], a0, a1, a2, a3, b0, b1);
            }
        }
    }
    __syncthreads();

    // ---- stage outputs (bias added) into sA as fp32, then pool ----
    float* sAf = (float*)sAu;
    #pragma unroll
    for (int nt = 0; nt < 4; nt++) {
        int col = warp_n * 32 + nt * 8 + 2 * tg;
        float bb0 = b[col], bb1 = b[col + 1];
        int r0_ = warp_m * 16 + gid;
        sAf[r0_ * 132 + col]     = acc[nt][0] + bb0;
        sAf[r0_ * 132 + col + 1] = acc[nt][1] + bb1;
        sAf[(r0_ + 8) * 132 + col]     = acc[nt][2] + bb0;
        sAf[(r0_ + 8) * 132 + col + 1] = acc[nt][3] + bb1;
    }
    __syncthreads();

    int j = t & 127, half = t >> 7;
    int rbeg = half * 16;
    int rend = min(rbeg + 16, N_NODES - row0);
    float pacc = 0.f;
    int cur = -1, cnt = 0;
    for (int r = rbeg; r < rend; r++) {
        int bb = __ldg(&batch[row0 + r]);
        if (bb != cur) {
            if (cur >= 0) {
                atomicAdd(&g_pool[cur * HID + j], pacc);
                if (j == 0) atomicAdd(&g_gcnt[cur], (float)cnt);
            }
            cur = bb; pacc = 0.f; cnt = 0;
        }
        pacc += sAf[r * 132 + j];
        cnt++;
    }
    if (cur >= 0) {
        atomicAdd(&g_pool[cur * HID + j], pacc);
        if (j == 0) atomicAdd(&g_gcnt[cur], (float)cnt);
    }
}

// ---------------- fused MLP head (clears g_pool / g_gcnt) ----------------
__global__ void __launch_bounds__(128) k_mlp(const float* __restrict__ Wm1,
                                             const float* __restrict__ bm1,
                                             const float* __restrict__ Wm2,
                                             const float* __restrict__ bm2,
                                             float* __restrict__ out) {
    __shared__ float grow[HID];
    __shared__ float r0[HID], r1[HID];
    int r = blockIdx.x;
    int j = threadIdx.x;
    grow[j] = g_pool[r * HID + j] / fmaxf(g_gcnt[r], 1.0f);
    g_pool[r * HID + j] = 0.f;
    __syncthreads();
    if (j == 0) g_gcnt[r] = 0.f;
    float acc = bm1[j];
    #pragma unroll 8
    for (int k = 0; k < HID; k++) acc += grow[k] * Wm1[k * HID + j];
    float h = fmaxf(acc, 0.f);
    r0[j] = h * Wm2[j * OUT_C + 0];
    r1[j] = h * Wm2[j * OUT_C + 1];
    __syncthreads();
    #pragma unroll
    for (int s = 64; s > 0; s >>= 1) {
        if (j < s) { r0[j] += r0[j + s]; r1[j] += r1[j + s]; }
        __syncthreads();
    }
    if (j == 0) {
        out[r * OUT_C + 0] = r0[0] + bm2[0];
        out[r * OUT_C + 1] = r1[0] + bm2[1];
    }
}

// ---------------- launch ----------------
static inline int cdiv(int a, int b) { return (a + b - 1) / b; }

extern "C" void kernel_launch(void* const* d_in, const int* in_sizes, int n_in,
                              void* d_out, int out_size) {
    const float* x    = (const float*)d_in[0];
    const int*   ei   = (const int*)d_in[1];
    const int*   src  = ei;
    const int*   dst  = ei + N_EDGES;
    const int*   batch= (const int*)d_in[2];
    const float* W1  = (const float*)d_in[3];
    const float* b1  = (const float*)d_in[4];
    const float* W2  = (const float*)d_in[5];
    const float* b2  = (const float*)d_in[6];
    const float* Wm1 = (const float*)d_in[7];
    const float* bm1 = (const float*)d_in[8];
    const float* Wm2 = (const float*)d_in[9];
    const float* bm2 = (const float*)d_in[10];
    float* out = (float*)d_out;

    const int T = 256;

    k_deg4    <<<cdiv(N_EDGES / 4, T), T>>>(dst);
    k_blocksum<<<SCAN_NBLK, 1024>>>();
    k_offsets <<<SCAN_NBLK, 1024>>>();
    k_csr     <<<cdiv(N_EDGES, T), T>>>(src, dst);

    k_fused1<<<cdiv(N_NODES, 32), 256>>>((const float4*)x, (const float4*)W1, b1);
    k_fused2<<<cdiv(N_NODES, 32), 256>>>((const float4*)W2, b2, batch);

    k_mlp<<<N_GRAPHS, HID>>>(Wm1, bm1, Wm2, bm2, out);
}

// round 17
// speedup vs baseline: 1.0834x; 1.0500x over previous
#include <cuda_runtime.h>
#include <cuda_fp16.h>
#include <math.h>

#define N_NODES 50000
#define N_EDGES 800000
#define IN_C    64
#define HID     128
#define OUT_C   2
#define N_GRAPHS 64
#define SCAN_NBLK 49   // ceil(50000/1024)

// ---------------- scratch (zero-init at load; kernels restore invariant) ----
__device__ __align__(16) int   g_cnt_e [N_NODES];
__device__ float    g_dinv  [N_NODES];
__device__ int      g_off   [N_NODES + 1];
__device__ int      g_cursor[N_NODES];
__device__ int2     g_csr2  [N_EDGES];        // {src, bit-cast dinv[src]}
__device__ int      g_part  [64];
__device__ unsigned g_h16   [N_NODES * 64];   // h as half2 pairs: 128 halves/node
__device__ float    g_pool  [N_GRAPHS * HID];
__device__ float    g_gcnt  [N_GRAPHS];

// ---------------- helpers ----------------
__device__ __forceinline__ unsigned f2tf(float f) {
    unsigned u;
    asm("cvt.rna.tf32.f32 %0, %1;" : "=r"(u) : "f"(f));
    return u;
}
__device__ __forceinline__ float4 h4_to_f4(uint2 u) {
    __half2 a = *(__half2*)&u.x;
    __half2 b = *(__half2*)&u.y;
    float2 fa = __half22float2(a);
    float2 fb = __half22float2(b);
    return make_float4(fa.x, fa.y, fb.x, fb.y);
}
__device__ __forceinline__ void mma_tf32(float* c, unsigned a0, unsigned a1,
                                         unsigned a2, unsigned a3,
                                         unsigned b0, unsigned b1) {
    asm volatile(
        "mma.sync.aligned.m16n8k8.row.col.f32.tf32.tf32.f32 "
        "{%0,%1,%2,%3}, {%4,%5,%6,%7}, {%8,%9}, {%0,%1,%2,%3};"
        : "+f"(c[0]), "+f"(c[1]), "+f"(c[2]), "+f"(c[3])
        : "r"(a0), "r"(a1), "r"(a2), "r"(a3), "r"(b0), "r"(b1));
}

// ---------------- degree (4 edges/thread) ----------------
__global__ void k_deg4(const int* __restrict__ dst) {
    int i4 = blockIdx.x * blockDim.x + threadIdx.x;
    if (i4 >= N_EDGES / 4) return;
    int4 d = ((const int4*)dst)[i4];
    atomicAdd(&g_cnt_e[d.x], 1);
    atomicAdd(&g_cnt_e[d.y], 1);
    atomicAdd(&g_cnt_e[d.z], 1);
    atomicAdd(&g_cnt_e[d.w], 1);
}

// ---------------- scan pass 1: per-block sums ----------------
__global__ void __launch_bounds__(1024) k_blocksum() {
    __shared__ int ws[32];
    int t = threadIdx.x, lane = t & 31, w = t >> 5;
    int i = blockIdx.x * 1024 + t;
    int v = (i < N_NODES) ? g_cnt_e[i] : 0;
    int s = v;
    #pragma unroll
    for (int d = 16; d > 0; d >>= 1) s += __shfl_xor_sync(0xffffffffu, s, d);
    if (lane == 0) ws[w] = s;
    __syncthreads();
    if (w == 0) {
        int x = ws[lane];
        #pragma unroll
        for (int d = 16; d > 0; d >>= 1) x += __shfl_xor_sync(0xffffffffu, x, d);
        if (lane == 0) g_part[blockIdx.x] = x;
    }
}

// ---------------- scan pass 2+3 fused: offsets; clears g_cnt_e ----------------
__global__ void __launch_bounds__(1024) k_offsets() {
    __shared__ int ws[32];
    __shared__ int sExcl[64];
    __shared__ int w0s;
    int t = threadIdx.x, lane = t & 31, w = t >> 5;

    int pv = 0, px = 0;
    if (w < 2) {
        pv = (t < SCAN_NBLK) ? g_part[t] : 0;
        px = pv;
        #pragma unroll
        for (int d = 1; d < 32; d <<= 1) {
            int y = __shfl_up_sync(0xffffffffu, px, d);
            if (lane >= d) px += y;
        }
        if (w == 0 && lane == 31) w0s = px;
    }
    __syncthreads();
    if (w < 2) sExcl[t] = px - pv + (w == 1 ? w0s : 0);

    int i = blockIdx.x * 1024 + t;
    int v = (i < N_NODES) ? g_cnt_e[i] : 0;
    int x = v;
    #pragma unroll
    for (int d = 1; d < 32; d <<= 1) {
        int y = __shfl_up_sync(0xffffffffu, x, d);
        if (lane >= d) x += y;
    }
    if (lane == 31) ws[w] = x;
    __syncthreads();
    if (w == 0) {
        int y = ws[lane];
        #pragma unroll
        for (int d = 1; d < 32; d <<= 1) {
            int z = __shfl_up_sync(0xffffffffu, y, d);
            if (lane >= d) y += z;
        }
        ws[lane] = y;
    }
    __syncthreads();
    int excl = sExcl[blockIdx.x] + (w ? ws[w - 1] : 0) + x - v;
    if (i < N_NODES) {
        g_off[i]    = excl;
        g_cursor[i] = excl;
        g_dinv[i]   = rsqrtf((float)v + 1.0f);
        g_cnt_e[i]  = 0;
    }
    if (i == 0) g_off[N_NODES] = N_EDGES;
}

// ---------------- CSR build (1 edge/thread): slot = {src, dinv[src]} ---------
__global__ void k_csr(const int* __restrict__ src, const int* __restrict__ dst) {
    int e = blockIdx.x * blockDim.x + threadIdx.x;
    if (e >= N_EDGES) return;
    int s = src[e];
    int d = dst[e];
    float ds = g_dinv[s];
    int pos = atomicAdd(&g_cursor[d], 1);
    g_csr2[pos] = make_int2(s, __float_as_int(ds));
}

// ---------------- fused layer 1: agg(x,64) + TF32 MMA + relu -> g_h16 --------
// 32 nodes/block. sA 32x68 (8.7 KB) + sW 32x136 (17.4 KB) = 26.1 KB -> 8 blk/SM.
__global__ void __launch_bounds__(256) k_fused1(const float4* __restrict__ X,
                                                const float4* __restrict__ W4,
                                                const float* __restrict__ b) {
    __shared__ __align__(16) unsigned sAu[32 * 68];
    __shared__ __align__(16) unsigned sWu[32 * 136];
    int t = threadIdx.x, lane = t & 31, w = t >> 5;
    int row0 = blockIdx.x * 32;

    // ---- aggregation (warp per node; halves interleave edges; pipelined) ----
    int c = lane & 15, half = lane >> 4;
    #pragma unroll 1
    for (int it = 0; it < 4; it++) {
        int n = row0 + it * 8 + w;
        int nl = it * 8 + w;
        if (n < N_NODES) {
            float dn = g_dinv[n];
            float4 acc = make_float4(0.f, 0.f, 0.f, 0.f);
            if (half == 0) {
                float4 v = X[(size_t)n * 16 + c];
                acc.x = dn * v.x; acc.y = dn * v.y; acc.z = dn * v.z; acc.w = dn * v.w;
            }
            int e  = g_off[n] + half;
            int e1 = g_off[n + 1];
            if (e < e1) {
                int2 p = g_csr2[e];
                while (true) {
                    int en = e + 2;
                    int2 pn = make_int2(0, 0);
                    bool more = (en < e1);
                    if (more) pn = g_csr2[en];
                    float ds = __int_as_float(p.y);
                    float4 v = X[(size_t)p.x * 16 + c];
                    acc.x += ds * v.x; acc.y += ds * v.y;
                    acc.z += ds * v.z; acc.w += ds * v.w;
                    if (!more) break;
                    e = en; p = pn;
                }
            }
            acc.x += __shfl_xor_sync(0xffffffffu, acc.x, 16);
            acc.y += __shfl_xor_sync(0xffffffffu, acc.y, 16);
            acc.z += __shfl_xor_sync(0xffffffffu, acc.z, 16);
            acc.w += __shfl_xor_sync(0xffffffffu, acc.w, 16);
            if (half == 0) {
                acc.x *= dn; acc.y *= dn; acc.z *= dn; acc.w *= dn;
                ((uint4*)sAu)[nl * 17 + c] =
                    make_uint4(f2tf(acc.x), f2tf(acc.y), f2tf(acc.z), f2tf(acc.w));
            }
        } else if (half == 0) {
            ((uint4*)sAu)[nl * 17 + c] = make_uint4(0u, 0u, 0u, 0u);
        }
    }

    // ---- GEMM via tf32 mma: warp grid 2x4 (16 rows x 32 cols each) ----
    int warp_m = w & 1, warp_n = w >> 1;
    int tg = lane & 3, gid = lane >> 2;
    float acc[4][4];
    #pragma unroll
    for (int nt = 0; nt < 4; nt++)
        #pragma unroll
        for (int i = 0; i < 4; i++) acc[nt][i] = 0.f;

    for (int kt0 = 0; kt0 < 64; kt0 += 32) {
        __syncthreads();
        for (int i = t; i < 32 * 32; i += 256) {
            int kr = i >> 5, n4 = i & 31;
            float4 wv = W4[(kt0 + kr) * 32 + n4];
            ((uint4*)sWu)[kr * 34 + n4] =
                make_uint4(f2tf(wv.x), f2tf(wv.y), f2tf(wv.z), f2tf(wv.w));
        }
        __syncthreads();
        #pragma unroll
        for (int ks = 0; ks < 4; ks++) {
            int kb = kt0 + ks * 8;
            int ar = warp_m * 16 + gid;
            unsigned a0 = sAu[ar * 68 + kb + tg];
            unsigned a1 = sAu[(ar + 8) * 68 + kb + tg];
            unsigned a2 = sAu[ar * 68 + kb + tg + 4];
            unsigned a3 = sAu[(ar + 8) * 68 + kb + tg + 4];
            int kl = ks * 8;
            #pragma unroll
            for (int nt = 0; nt < 4; nt++) {
                int nc = warp_n * 32 + nt * 8 + gid;
                unsigned b0 = sWu[(kl + tg) * 136 + nc];
                unsigned b1 = sWu[(kl + tg + 4) * 136 + nc];
                mma_tf32(acc[nt], a0, a1, a2, a3, b0, b1);
            }
        }
    }

    // ---- epilogue: bias + relu -> g_h16 (half2 per 2 cols) ----
    #pragma unroll
    for (int nt = 0; nt < 4; nt++) {
        int col = warp_n * 32 + nt * 8 + 2 * tg;
        float bb0 = b[col], bb1 = b[col + 1];
        int gr0 = row0 + warp_m * 16 + gid;
        if (gr0 < N_NODES) {
            __half2 hv = __floats2half2_rn(fmaxf(acc[nt][0] + bb0, 0.f),
                                           fmaxf(acc[nt][1] + bb1, 0.f));
            g_h16[(size_t)gr0 * 64 + (col >> 1)] = *(unsigned*)&hv;
        }
        int gr1 = gr0 + 8;
        if (gr1 < N_NODES) {
            __half2 hv = __floats2half2_rn(fmaxf(acc[nt][2] + bb0, 0.f),
                                           fmaxf(acc[nt][3] + bb1, 0.f));
            g_h16[(size_t)gr1 * 64 + (col >> 1)] = *(unsigned*)&hv;
        }
    }
}

// ---------------- fused layer 2: agg(g_h16,128) + TF32 MMA + mean-pool -------
// 32 nodes/block. sA 32x132 (16.9 KB) + sW 16x136 (8.7 KB) = 25.6 KB -> 8 blk/SM.
__global__ void __launch_bounds__(256) k_fused2(const float4* __restrict__ W4,
                                                const float* __restrict__ b,
                                                const int* __restrict__ batch) {
    __shared__ __align__(16) unsigned sAu[32 * 132];
    __shared__ __align__(16) unsigned sWu[16 * 136];
    int t = threadIdx.x, lane = t & 31, w = t >> 5;
    int row0 = blockIdx.x * 32;
    const uint2* H16 = (const uint2*)g_h16;

    // ---- aggregation (warp per node; lane = 4-feat chunk; pipelined pairs) ----
    #pragma unroll 1
    for (int it = 0; it < 4; it++) {
        int n = row0 + it * 8 + w;
        int nl = it * 8 + w;
        if (n < N_NODES) {
            float dn = g_dinv[n];
            float4 v = h4_to_f4(H16[(size_t)n * 32 + lane]);
            float4 acc;
            acc.x = dn * v.x; acc.y = dn * v.y; acc.z = dn * v.z; acc.w = dn * v.w;
            int beg = g_off[n];
            int e1  = g_off[n + 1];
            int cntE = e1 - beg;
            int pairs = cntE >> 1;
            if (pairs > 0) {
                int ee = beg;
                int2 p0 = g_csr2[ee], p1 = g_csr2[ee + 1];
                for (int p = 0; p < pairs; p++) {
                    int2 np0 = make_int2(0, 0), np1 = make_int2(0, 0);
                    if (p + 1 < pairs) {
                        np0 = g_csr2[ee + 2]; np1 = g_csr2[ee + 3];
                    }
                    float d0 = __int_as_float(p0.y), d1 = __int_as_float(p1.y);
                    float4 v0 = h4_to_f4(H16[(size_t)p0.x * 32 + lane]);
                    float4 v1 = h4_to_f4(H16[(size_t)p1.x * 32 + lane]);
                    acc.x += d0 * v0.x + d1 * v1.x;
                    acc.y += d0 * v0.y + d1 * v1.y;
                    acc.z += d0 * v0.z + d1 * v1.z;
                    acc.w += d0 * v0.w + d1 * v1.w;
                    p0 = np0; p1 = np1; ee += 2;
                }
            }
            if (cntE & 1) {
                int2 p = g_csr2[beg + (cntE & ~1)];
                float d0 = __int_as_float(p.y);
                float4 v0 = h4_to_f4(H16[(size_t)p.x * 32 + lane]);
                acc.x += d0 * v0.x; acc.y += d0 * v0.y;
                acc.z += d0 * v0.z; acc.w += d0 * v0.w;
            }
            acc.x *= dn; acc.y *= dn; acc.z *= dn; acc.w *= dn;
            ((uint4*)sAu)[nl * 33 + lane] =
                make_uint4(f2tf(acc.x), f2tf(acc.y), f2tf(acc.z), f2tf(acc.w));
        } else {
            ((uint4*)sAu)[nl * 33 + lane] = make_uint4(0u, 0u, 0u, 0u);
        }
    }

    // ---- GEMM via tf32 mma: warp grid 2x4 ----
    int warp_m = w & 1, warp_n = w >> 1;
    int tg = lane & 3, gid = lane >> 2;
    float acc[4][4];
    #pragma unroll
    for (int nt = 0; nt < 4; nt++)
        #pragma unroll
        for (int i = 0; i < 4; i++) acc[nt][i] = 0.f;

    for (int kt0 = 0; kt0 < 128; kt0 += 16) {
        __syncthreads();
        for (int i = t; i < 16 * 32; i += 256) {
            int kr = i >> 5, n4 = i & 31;
            float4 wv = W4[(kt0 + kr) * 32 + n4];
            ((uint4*)sWu)[kr * 34 + n4] =
                make_uint4(f2tf(wv.x), f2tf(wv.y), f2tf(wv.z), f2tf(wv.w));
        }
        __syncthreads();
        #pragma unroll
        for (int ks = 0; ks < 2; ks++) {
            int kb = kt0 + ks * 8;
            int ar = warp_m * 16 + gid;
            unsigned a0 = sAu[ar * 132 + kb + tg];
            unsigned a1 = sAu[(ar + 8) * 132 + kb + tg];
            unsigned a2 = sAu[ar * 132 + kb + tg + 4];
            unsigned a3 = sAu[(ar + 8) * 132 + kb + tg + 4];
            int kl = ks * 8;
            #pragma unroll
            for (int nt = 0; nt < 4; nt++) {
                int nc = warp_n * 32 + nt * 8 + gid;
                unsigned b0 = sWu[(kl + tg) * 136 + nc];
                unsigned b1 = sWu[(kl + tg + 4) * 136 + nc];
                mma_tf32(acc[nt], a0, a1, a2, a3, b0, b1);
            }
        }
    }
    __syncthreads();

    // ---- stage outputs (bias added) into sA as fp32, then pool ----
    float* sAf = (float*)sAu;
    #pragma unroll
    for (int nt = 0; nt < 4; nt++) {
        int col = warp_n * 32 + nt * 8 + 2 * tg;
        float bb0 = b[col], bb1 = b[col + 1];
        int r0_ = warp_m * 16 + gid;
        sAf[r0_ * 132 + col]     = acc[nt][0] + bb0;
        sAf[r0_ * 132 + col + 1] = acc[nt][1] + bb1;
        sAf[(r0_ + 8) * 132 + col]     = acc[nt][2] + bb0;
        sAf[(r0_ + 8) * 132 + col + 1] = acc[nt][3] + bb1;
    }
    __syncthreads();

    int j = t & 127, half = t >> 7;
    int rbeg = half * 16;
    int rend = min(rbeg + 16, N_NODES - row0);
    float pacc = 0.f;
    int cur = -1, cnt = 0;
    for (int r = rbeg; r < rend; r++) {
        int bb = __ldg(&batch[row0 + r]);
        if (bb != cur) {
            if (cur >= 0) {
                atomicAdd(&g_pool[cur * HID + j], pacc);
                if (j == 0) atomicAdd(&g_gcnt[cur], (float)cnt);
            }
            cur = bb; pacc = 0.f; cnt = 0;
        }
        pacc += sAf[r * 132 + j];
        cnt++;
    }
    if (cur >= 0) {
        atomicAdd(&g_pool[cur * HID + j], pacc);
        if (j == 0) atomicAdd(&g_gcnt[cur], (float)cnt);
    }
}

// ---------------- fused MLP head (clears g_pool / g_gcnt) ----------------
__global__ void __launch_bounds__(128) k_mlp(const float* __restrict__ Wm1,
                                             const float* __restrict__ bm1,
                                             const float* __restrict__ Wm2,
                                             const float* __restrict__ bm2,
                                             float* __restrict__ out) {
    __shared__ float grow[HID];
    __shared__ float r0[HID], r1[HID];
    int r = blockIdx.x;
    int j = threadIdx.x;
    grow[j] = g_pool[r * HID + j] / fmaxf(g_gcnt[r], 1.0f);
    g_pool[r * HID + j] = 0.f;
    __syncthreads();
    if (j == 0) g_gcnt[r] = 0.f;
    float acc = bm1[j];
    #pragma unroll 8
    for (int k = 0; k < HID; k++) acc += grow[k] * Wm1[k * HID + j];
    float h = fmaxf(acc, 0.f);
    r0[j] = h * Wm2[j * OUT_C + 0];
    r1[j] = h * Wm2[j * OUT_C + 1];
    __syncthreads();
    #pragma unroll
    for (int s = 64; s > 0; s >>= 1) {
        if (j < s) { r0[j] += r0[j + s]; r1[j] += r1[j + s]; }
        __syncthreads();
    }
    if (j == 0) {
        out[r * OUT_C + 0] = r0[0] + bm2[0];
        out[r * OUT_C + 1] = r1[0] + bm2[1];
    }
}

// ---------------- launch ----------------
static inline int cdiv(int a, int b) { return (a + b - 1) / b; }

extern "C" void kernel_launch(void* const* d_in, const int* in_sizes, int n_in,
                              void* d_out, int out_size) {
    const float* x    = (const float*)d_in[0];
    const int*   ei   = (const int*)d_in[1];
    const int*   src  = ei;
    const int*   dst  = ei + N_EDGES;
    const int*   batch= (const int*)d_in[2];
    const float* W1  = (const float*)d_in[3];
    const float* b1  = (const float*)d_in[4];
    const float* W2  = (const float*)d_in[5];
    const float* b2  = (const float*)d_in[6];
    const float* Wm1 = (const float*)d_in[7];
    const float* bm1 = (const float*)d_in[8];
    const float* Wm2 = (const float*)d_in[9];
    const float* bm2 = (const float*)d_in[10];
    float* out = (float*)d_out;

    const int T = 256;

    k_deg4    <<<cdiv(N_EDGES / 4, T), T>>>(dst);
    k_blocksum<<<SCAN_NBLK, 1024>>>();
    k_offsets <<<SCAN_NBLK, 1024>>>();
    k_csr     <<<cdiv(N_EDGES, T), T>>>(src, dst);

    k_fused1<<<cdiv(N_NODES, 32), 256>>>((const float4*)x, (const float4*)W1, b1);
    k_fused2<<<cdiv(N_NODES, 32), 256>>>((const float4*)W2, b2, batch);

    k_mlp<<<N_GRAPHS, HID>>>(Wm1, bm1, Wm2, bm2, out);
}